// round 8
// baseline (speedup 1.0000x reference)
#include <cuda_runtime.h>
#include <cuda_bf16.h>
#include <cstdint>
#include <math.h>

#define NN 30000
#define KK 15
#define TT 400
#define NCC 5
#define GG 8                      // rows per block in main kernel
#define ROWB8 400                 // 400 B per u8 row
#define STAGEBYTES (KK * ROWB8)   // 6000 B (15 neighbor rows)
#define T4 (TT / 4)               // 100 chunks of 4 t-values

// ---------------- scratch (device globals: allocation-free) ----------------
__device__ __align__(32) __nv_bfloat16 g_emd[NN * TT];  // bf16 table (self rows)
__device__ __align__(32) unsigned char g_emd8[NN * TT]; // u8 table (neighbor rows)
__device__ float g_scl[NN];            // per-row dequant scale (rowmax/127)
__device__ float g_W[NN * 16];         // [0]=(1-ew), [1..15]=combined nbr weights
__device__ float g_UV[NN * 10];        // u[5], v[5]
__device__ float g_tab[2 * NCC * TT];  // sin table, then cos table (fp32)

// ---------------- helpers ----------------
__device__ __forceinline__ uint32_t smem_u32(const void* p) {
    uint32_t a;
    asm("{ .reg .u64 t; cvta.to.shared.u64 t, %1; cvt.u32.u64 %0, t; }"
        : "=r"(a) : "l"(p));
    return a;
}
__device__ __forceinline__ void mbar_init(uint32_t mbar, uint32_t count) {
    asm volatile("mbarrier.init.shared.b64 [%0], %1;" :: "r"(mbar), "r"(count) : "memory");
}
__device__ __forceinline__ void mbar_expect_tx(uint32_t mbar, uint32_t bytes) {
    asm volatile("mbarrier.arrive.expect_tx.shared.b64 _, [%0], %1;"
                 :: "r"(mbar), "r"(bytes) : "memory");
}
__device__ __forceinline__ void mbar_wait(uint32_t mbar, uint32_t parity) {
    asm volatile(
        "{\n\t"
        ".reg .pred P;\n\t"
        "LAB_WAIT_%=:\n\t"
        "mbarrier.try_wait.parity.acquire.cta.shared::cta.b64 P, [%0], %1, 0x989680;\n\t"
        "@P bra LAB_DONE_%=;\n\t"
        "bra LAB_WAIT_%=;\n\t"
        "LAB_DONE_%=:\n\t"
        "}"
        :: "r"(mbar), "r"(parity) : "memory");
}
__device__ __forceinline__ void bulk_g2s(uint32_t dst, const void* src,
                                         uint32_t bytes, uint32_t mbar) {
    asm volatile(
        "cp.async.bulk.shared::cluster.global.mbarrier::complete_tx::bytes "
        "[%0], [%1], %2, [%3];"
        :: "r"(dst), "l"(src), "r"(bytes), "r"(mbar) : "memory");
}
// bf16 unpack (self row): lo via shift; hi uses raw word (below-ulp garbage)
__device__ __forceinline__ float bf_lo(uint32_t u) { return __uint_as_float(u << 16); }
__device__ __forceinline__ float bf_hi(uint32_t u) { return __uint_as_float(u); }
// u8 -> float(u) - 128, exact: place byte into 2^23-biased float, subtract
#define C0 (-8388736.0f)  // -(8388608 + 128)
__device__ __forceinline__ float u8f(uint32_t raw, int k) {
    return __uint_as_float(__byte_perm(raw, 0x4B000000u, 0x7440u | (uint32_t)k)) + C0;
}

// ------------- fused pre-pass: UV first, W, TAB, then emdsum(bf16+u8) -------
#define ROWS_PER_BLK 5                        // 5 rows x 50 threads = 250
#define NB_EMD    (NN / ROWS_PER_BLK)         // 6000
#define NB_W      ((NN * 16 + 255) / 256)
#define NB_UV     ((NN * NCC + 255) / 256)
#define NB_TAB    ((NCC * TT + 255) / 256)
#define NB_PRE    (NB_EMD + NB_W + NB_UV + NB_TAB)

__global__ void __launch_bounds__(256)
k_pre(const float* __restrict__ emd,
      const float* __restrict__ nbr_w,
      const float* __restrict__ loc_w,
      const float* __restrict__ esw,
      const float* __restrict__ lsw,
      const float* __restrict__ amp,
      const float* __restrict__ ph,
      const int*   __restrict__ idx,
      const float* __restrict__ tv,
      const float* __restrict__ per) {
    int b = blockIdx.x;
    int tid = threadIdx.x;
    if (b < NB_UV) {
        int i = b * 256 + tid;
        if (i >= NN * NCC) return;
        int n = i / NCC;
        int c = i - n * NCC;
        float sa = 0.0f, ss = 0.0f, sc = 0.0f;
#pragma unroll
        for (int k = 0; k < KK; k++) {
            int m = idx[n * KK + k];
            float w = nbr_w[n * KK + k];
            sa += w * amp[m * NCC + c];
            float p = ph[m * NCC + c];
            float s, co;
            __sincosf(p, &s, &co);
            ss += w * s;
            sc += w * co;
        }
        float A = 0.8f * amp[i] + 0.2f * sa;
        float P = 0.8f * ph[i] + 0.2f * atan2f(ss, sc);
        float sp, cp;
        __sincosf(P, &sp, &cp);
        g_UV[n * 10 + c] = A * cp;
        g_UV[n * 10 + 5 + c] = A * sp;
        return;
    }
    b -= NB_UV;
    if (b < NB_W) {
        int i = b * 256 + tid;
        if (i >= NN * 16) return;
        int n = i >> 4;
        int j = i & 15;
        float ew = 1.0f / (1.0f + __expf(-esw[n]));
        if (j == 0) { g_W[i] = 1.0f - ew; return; }
        float lw = 1.0f / (1.0f + __expf(-lsw[n]));
        int k = j - 1;
        g_W[i] = ew * lw * loc_w[n * KK + k] + ew * (1.0f - lw) * nbr_w[n * KK + k];
        return;
    }
    b -= NB_W;
    if (b < NB_TAB) {
        int i = b * 256 + tid;
        if (i >= NCC * TT) return;
        int c = i / TT;
        int t = i - c * TT;
        float p = fminf(fmaxf(per[c], 15.0f), 350.0f);
        float arg = 6.283185307179586f * tv[t] / p;
        float s, co;
        sincosf(arg, &s, &co);
        g_tab[i] = s;
        g_tab[NCC * TT + i] = co;
        return;
    }
    b -= NB_TAB;
    {
        // ---- emdsum: 5 rows x 50 threads; write bf16 + u8(+scale) ----
        __shared__ int s_max[ROWS_PER_BLK];
        if (tid < ROWS_PER_BLK) s_max[tid] = 0;
        __syncthreads();
        bool on = (tid < ROWS_PER_BLK * 50);
        int r = tid / 50;       // row within block
        int l = tid % 50;       // 8-value chunk within row
        int n = b * ROWS_PER_BLK + r;
        float v[8];
        if (on) {
            const float4* base = reinterpret_cast<const float4*>(emd + (size_t)n * 4 * TT);
#pragma unroll
            for (int e = 0; e < 8; e++) v[e] = 0.0f;
#pragma unroll
            for (int c = 0; c < 4; c++) {
                float4 a = base[c * T4 + 2 * l];
                float4 bb = base[c * T4 + 2 * l + 1];
                v[0] += a.x;  v[1] += a.y;  v[2] += a.z;  v[3] += a.w;
                v[4] += bb.x; v[5] += bb.y; v[6] += bb.z; v[7] += bb.w;
            }
            float am = 0.0f;
#pragma unroll
            for (int e = 0; e < 8; e++) am = fmaxf(am, fabsf(v[e]));
            atomicMax(&s_max[r], __float_as_int(am));
        }
        __syncthreads();
        if (!on) return;
        float mx = fmaxf(__int_as_float(s_max[r]), 1e-20f);
        float inv = 127.0f / mx;
        // bf16 row
        __nv_bfloat162 h[4];
#pragma unroll
        for (int e = 0; e < 4; e++)
            h[e] = __floats2bfloat162_rn(v[2 * e], v[2 * e + 1]);
        reinterpret_cast<uint4*>(g_emd + (size_t)n * TT)[l] =
            *reinterpret_cast<uint4*>(h);
        // u8 row (value + 128)
        uint32_t p0 = 0, p1 = 0;
#pragma unroll
        for (int e = 0; e < 4; e++) {
            uint32_t q = (uint32_t)(int)(rintf(v[e] * inv) + 128.0f);
            p0 |= (q & 0xFFu) << (8 * e);
        }
#pragma unroll
        for (int e = 0; e < 4; e++) {
            uint32_t q = (uint32_t)(int)(rintf(v[4 + e] * inv) + 128.0f);
            p1 |= (q & 0xFFu) << (8 * e);
        }
        uint2 pk = make_uint2(p0, p1);
        reinterpret_cast<uint2*>(g_emd8 + (size_t)n * TT)[l] = pk;
        if (l == 0) g_scl[n] = mx * (1.0f / 127.0f);
    }
}

// ------ main kernel: TMA u8 neighbor gather + bf16 self LDG + fused output --
extern __shared__ __align__(16) unsigned char s_buf[];  // 2 * 6000 B

__global__ void __launch_bounds__(128, 8)
k_main(const int* __restrict__ idx,
       const float* __restrict__ coff,
       const float* __restrict__ ltr,
       const float* __restrict__ tv,
       float* __restrict__ out) {
    __shared__ __align__(8) unsigned long long s_full[2];
    __shared__ int   s_idx[GG][KK];
    __shared__ float s_W[GG][16];
    __shared__ float s_Wq[GG][KK];   // weight * dequant-scale per neighbor
    __shared__ float s_UV[GG][10];
    __shared__ float s_off[GG];
    __shared__ float s_tr[GG];

    int tid = threadIdx.x;
    int n0 = blockIdx.x * GG;

    if (tid < GG * KK) s_idx[tid / KK][tid % KK] = idx[n0 * KK + tid];
    if (tid < GG * 16) s_W[tid >> 4][tid & 15] = g_W[n0 * 16 + tid];
    if (tid < GG * 10) s_UV[tid / 10][tid % 10] = g_UV[n0 * 10 + tid];
    if (tid < GG) { s_off[tid] = coff[n0 + tid]; s_tr[tid] = ltr[n0 + tid]; }

    uint32_t full0 = smem_u32(&s_full[0]);
    uint32_t bufb  = smem_u32(s_buf);
    if (tid == 0) {
        mbar_init(full0, 1);
        mbar_init(full0 + 8, 1);
        asm volatile("fence.proxy.async.shared::cta;" ::: "memory");
    }

    // per-thread register-resident harmonic table + time values (fp32)
    float4 st[NCC], ct[NCC], tv4;
    bool act = (tid < T4);
    if (act) {
#pragma unroll
        for (int c = 0; c < NCC; c++) {
            st[c] = reinterpret_cast<const float4*>(g_tab + c * TT)[tid];
            ct[c] = reinterpret_cast<const float4*>(g_tab + NCC * TT + c * TT)[tid];
        }
        tv4 = reinterpret_cast<const float4*>(tv)[tid];
    }
    __syncthreads();  // s_idx/s_W visible; mbarriers initialized

    // fold dequant scale into neighbor weights
    if (tid < GG * KK) {
        int g = tid / KK, k = tid % KK;
        s_Wq[g][k] = s_W[g][k + 1] * g_scl[s_idx[g][k]];
    }

    auto issue = [&](int s) {
        uint32_t dst = bufb + (uint32_t)(s & 1) * STAGEBYTES;
        uint32_t mb  = full0 + (uint32_t)(s & 1) * 8;
        mbar_expect_tx(mb, STAGEBYTES);
#pragma unroll
        for (int k = 0; k < KK; k++) {
            bulk_g2s(dst + (uint32_t)k * ROWB8,
                     g_emd8 + (size_t)s_idx[s][k] * TT, ROWB8, mb);
        }
    };

    __syncthreads();  // s_Wq visible

    if (tid == 0) issue(0);

    for (int i = 0; i < GG; i++) {
        if (tid == 0 && i + 1 < GG) issue(i + 1);

        int n = n0 + i;
        uint2 selfraw;
        float4 acc;
        if (act) {
            // independent self-row LDG (bf16), issued before the TMA wait
            selfraw = *reinterpret_cast<const uint2*>(g_emd + (size_t)n * TT + 4 * tid);
            float off = s_off[i], tr = s_tr[i];
            acc.x = fmaf(tr, tv4.x, off);
            acc.y = fmaf(tr, tv4.y, off);
            acc.z = fmaf(tr, tv4.z, off);
            acc.w = fmaf(tr, tv4.w, off);
#pragma unroll
            for (int c = 0; c < NCC; c++) {
                float u = s_UV[i][c], v = s_UV[i][5 + c];
                acc.x = fmaf(u, st[c].x, fmaf(v, ct[c].x, acc.x));
                acc.y = fmaf(u, st[c].y, fmaf(v, ct[c].y, acc.y));
                acc.z = fmaf(u, st[c].z, fmaf(v, ct[c].z, acc.z));
                acc.w = fmaf(u, st[c].w, fmaf(v, ct[c].w, acc.w));
            }
        }

        mbar_wait(full0 + (uint32_t)(i & 1) * 8, (uint32_t)((i >> 1) & 1));

        if (act) {
            const uint32_t* rows8 = reinterpret_cast<const uint32_t*>(
                s_buf + (size_t)(i & 1) * STAGEBYTES);
            // 15 neighbor rows, u8, scale-folded weights
#pragma unroll
            for (int j = 0; j < KK; j++) {
                uint32_t raw = rows8[j * 100 + tid];
                float w = s_Wq[i][j];
                acc.x = fmaf(w, u8f(raw, 0), acc.x);
                acc.y = fmaf(w, u8f(raw, 1), acc.y);
                acc.z = fmaf(w, u8f(raw, 2), acc.z);
                acc.w = fmaf(w, u8f(raw, 3), acc.w);
            }
            // self row (bf16)
            {
                float w = s_W[i][0];
                acc.x = fmaf(w, bf_lo(selfraw.x), acc.x);
                acc.y = fmaf(w, bf_hi(selfraw.x), acc.y);
                acc.z = fmaf(w, bf_lo(selfraw.y), acc.z);
                acc.w = fmaf(w, bf_hi(selfraw.y), acc.w);
            }
            reinterpret_cast<float4*>(out + (size_t)n * TT)[tid] = acc;
        }
        __syncthreads();  // all threads done reading buffer i&1
    }
}

// ---------------- launch ----------------
extern "C" void kernel_launch(void* const* d_in, const int* in_sizes, int n_in,
                              void* d_out, int out_size) {
    const float* tv   = (const float*)d_in[0];
    const float* coff = (const float*)d_in[1];
    const float* ltr  = (const float*)d_in[2];
    const float* emd  = (const float*)d_in[3];
    const int*   idx  = (const int*)  d_in[4];
    const float* nw   = (const float*)d_in[5];
    const float* lwv  = (const float*)d_in[6];
    const float* amp  = (const float*)d_in[7];
    const float* ph   = (const float*)d_in[8];
    const float* per  = (const float*)d_in[9];
    const float* esw  = (const float*)d_in[10];
    const float* lsw  = (const float*)d_in[11];
    float* out = (float*)d_out;

    k_pre<<<NB_PRE, 256>>>(emd, nw, lwv, esw, lsw, amp, ph, idx, tv, per);

    cudaFuncSetAttribute(k_main, cudaFuncAttributeMaxDynamicSharedMemorySize,
                         2 * STAGEBYTES);
    k_main<<<NN / GG, 128, 2 * STAGEBYTES>>>(idx, coff, ltr, tv, out);
}

// round 10
// speedup vs baseline: 1.3704x; 1.3704x over previous
#include <cuda_runtime.h>
#include <cuda.h>
#include <cuda_bf16.h>
#include <cstdint>
#include <math.h>

#define NN 30000
#define KK 15
#define TT 400
#define NCC 5
#define GG 8                      // rows per block in main kernel
#define ROWS 16                   // self + 15 neighbors
#define ROWBYTES (TT * 2)         // 800 B per bf16 row
#define STAGEBYTES (ROWS * ROWBYTES)  // 12800 B
#define T4 (TT / 4)               // 100 chunks of 4 t-values

// ---------------- scratch (device globals: allocation-free) ----------------
__device__ __align__(32) __nv_bfloat16 g_emd[NN * TT];  // summed EMD bf16 (24 MB)
__device__ float g_W[NN * 16];
__device__ float g_UV[NN * 10];
__device__ float g_tab[2 * NCC * TT];

// ---------------- helpers ----------------
__device__ __forceinline__ uint32_t smem_u32(const void* p) {
    uint32_t a;
    asm("{ .reg .u64 t; cvta.to.shared.u64 t, %1; cvt.u32.u64 %0, t; }"
        : "=r"(a) : "l"(p));
    return a;
}
__device__ __forceinline__ void mbar_init(uint32_t mbar, uint32_t count) {
    asm volatile("mbarrier.init.shared.b64 [%0], %1;" :: "r"(mbar), "r"(count) : "memory");
}
__device__ __forceinline__ void mbar_expect_tx(uint32_t mbar, uint32_t bytes) {
    asm volatile("mbarrier.arrive.expect_tx.shared.b64 _, [%0], %1;"
                 :: "r"(mbar), "r"(bytes) : "memory");
}
__device__ __forceinline__ void mbar_wait(uint32_t mbar, uint32_t parity) {
    asm volatile(
        "{\n\t"
        ".reg .pred P;\n\t"
        "LAB_WAIT_%=:\n\t"
        "mbarrier.try_wait.parity.acquire.cta.shared::cta.b64 P, [%0], %1, 0x989680;\n\t"
        "@P bra LAB_DONE_%=;\n\t"
        "bra LAB_WAIT_%=;\n\t"
        "LAB_DONE_%=:\n\t"
        "}"
        :: "r"(mbar), "r"(parity) : "memory");
}
__device__ __forceinline__ void bulk_g2s(uint32_t dst, const void* src,
                                         uint32_t bytes, uint32_t mbar) {
    asm volatile(
        "cp.async.bulk.shared::cluster.global.mbarrier::complete_tx::bytes "
        "[%0], [%1], %2, [%3];"
        :: "r"(dst), "l"(src), "r"(bytes), "r"(mbar) : "memory");
}
// gather4 (sm_103: destination MUST be .shared::cta, not ::cluster):
// one request loads 4 scattered rows (r0..r3), boxDim[0] u32 cols each
__device__ __forceinline__ void g4(uint32_t dst, const CUtensorMap* tmap,
                                   int r0, int r1, int r2, int r3, uint32_t mbar) {
    asm volatile(
        "cp.async.bulk.tensor.2d.tile::gather4.shared::cta.global"
        ".mbarrier::complete_tx::bytes [%0], [%1, {%2, %3, %4, %5, %6}], [%7];"
        :: "r"(dst), "l"(tmap), "r"(0), "r"(r0), "r"(r1), "r"(r2), "r"(r3),
           "r"(mbar) : "memory");
}
// bf16 unpack: lo via shift; hi uses raw word (garbage low bits below bf16 ulp)
__device__ __forceinline__ float bf_lo(uint32_t u) { return __uint_as_float(u << 16); }
__device__ __forceinline__ float bf_hi(uint32_t u) { return __uint_as_float(u); }

// ------------- fused pre-pass: UV first, W, TAB, then emdsum(bf16) ----------
#define EMD_WORK  (NN * (TT / 8))
#define NB_EMD    ((EMD_WORK + 255) / 256)
#define NB_W      ((NN * 16 + 255) / 256)
#define NB_UV     ((NN * NCC + 255) / 256)
#define NB_TAB    ((NCC * TT + 255) / 256)
#define NB_PRE    (NB_EMD + NB_W + NB_UV + NB_TAB)

__global__ void __launch_bounds__(256)
k_pre(const float* __restrict__ emd,
      const float* __restrict__ nbr_w,
      const float* __restrict__ loc_w,
      const float* __restrict__ esw,
      const float* __restrict__ lsw,
      const float* __restrict__ amp,
      const float* __restrict__ ph,
      const int*   __restrict__ idx,
      const float* __restrict__ tv,
      const float* __restrict__ per) {
    int b = blockIdx.x;
    if (b < NB_UV) {
        int i = b * 256 + threadIdx.x;
        if (i >= NN * NCC) return;
        int n = i / NCC;
        int c = i - n * NCC;
        float sa = 0.0f, ss = 0.0f, sc = 0.0f;
#pragma unroll
        for (int k = 0; k < KK; k++) {
            int m = idx[n * KK + k];
            float w = nbr_w[n * KK + k];
            sa += w * amp[m * NCC + c];
            float p = ph[m * NCC + c];
            float s, co;
            __sincosf(p, &s, &co);
            ss += w * s;
            sc += w * co;
        }
        float A = 0.8f * amp[i] + 0.2f * sa;
        float P = 0.8f * ph[i] + 0.2f * atan2f(ss, sc);
        float sp, cp;
        __sincosf(P, &sp, &cp);
        g_UV[n * 10 + c] = A * cp;
        g_UV[n * 10 + 5 + c] = A * sp;
        return;
    }
    b -= NB_UV;
    if (b < NB_W) {
        int i = b * 256 + threadIdx.x;
        if (i >= NN * 16) return;
        int n = i >> 4;
        int j = i & 15;
        float ew = 1.0f / (1.0f + __expf(-esw[n]));
        if (j == 0) { g_W[i] = 1.0f - ew; return; }
        float lw = 1.0f / (1.0f + __expf(-lsw[n]));
        int k = j - 1;
        g_W[i] = ew * lw * loc_w[n * KK + k] + ew * (1.0f - lw) * nbr_w[n * KK + k];
        return;
    }
    b -= NB_W;
    if (b < NB_TAB) {
        int i = b * 256 + threadIdx.x;
        if (i >= NCC * TT) return;
        int c = i / TT;
        int t = i - c * TT;
        float p = fminf(fmaxf(per[c], 15.0f), 350.0f);
        float arg = 6.283185307179586f * tv[t] / p;
        float s, co;
        sincosf(arg, &s, &co);
        g_tab[i] = s;
        g_tab[NCC * TT + i] = co;
        return;
    }
    b -= NB_TAB;
    {
        int i = b * 256 + threadIdx.x;
        if (i >= EMD_WORK) return;
        int n = i / (TT / 8);
        int t8 = i - n * (TT / 8);
        const float4* base = reinterpret_cast<const float4*>(emd + (size_t)n * 4 * TT);
        float r[8];
#pragma unroll
        for (int e = 0; e < 8; e++) r[e] = 0.0f;
#pragma unroll
        for (int c = 0; c < 4; c++) {
            float4 a = base[c * T4 + 2 * t8];
            float4 bb = base[c * T4 + 2 * t8 + 1];
            r[0] += a.x;  r[1] += a.y;  r[2] += a.z;  r[3] += a.w;
            r[4] += bb.x; r[5] += bb.y; r[6] += bb.z; r[7] += bb.w;
        }
        __nv_bfloat162 h[4];
#pragma unroll
        for (int e = 0; e < 4; e++)
            h[e] = __floats2bfloat162_rn(r[2 * e], r[2 * e + 1]);
        reinterpret_cast<uint4*>(g_emd + (size_t)n * TT)[t8] =
            *reinterpret_cast<uint4*>(h);
    }
}

// ======== shared compute body for both main kernels =========================
extern __shared__ __align__(1024) __nv_bfloat16 s_buf[];  // 2 * 12800 B

struct MainSmem {
    unsigned long long full[2];
    int   idxs[GG][ROWS];   // [0]=self, [1..15]=neighbors
    float W[GG][16];
    float UV[GG][10];
    float off[GG];
    float tr[GG];
};

__device__ __forceinline__ void main_prologue(
    MainSmem& sm, const int* __restrict__ idx,
    const float* __restrict__ coff, const float* __restrict__ ltr,
    const float* __restrict__ tv, int n0, int tid,
    float4* st, float4* ct, float4& tv4, bool act) {
    if (tid < GG * KK) sm.idxs[tid / KK][tid % KK + 1] = idx[n0 * KK + tid];
    if (tid < GG * 16) sm.W[tid >> 4][tid & 15] = g_W[n0 * 16 + tid];
    if (tid < GG * 10) sm.UV[tid / 10][tid % 10] = g_UV[n0 * 10 + tid];
    if (tid < GG) {
        sm.off[tid] = coff[n0 + tid];
        sm.tr[tid] = ltr[n0 + tid];
        sm.idxs[tid][0] = n0 + tid;
    }
    if (tid == 0) {
        uint32_t f0 = smem_u32(&sm.full[0]);
        mbar_init(f0, 1);
        mbar_init(f0 + 8, 1);
        asm volatile("fence.proxy.async.shared::cta;" ::: "memory");
    }
    if (act) {
#pragma unroll
        for (int c = 0; c < NCC; c++) {
            st[c] = reinterpret_cast<const float4*>(g_tab + c * TT)[tid];
            ct[c] = reinterpret_cast<const float4*>(g_tab + NCC * TT + c * TT)[tid];
        }
        tv4 = reinterpret_cast<const float4*>(tv)[tid];
    }
}

__device__ __forceinline__ void stage_compute(
    MainSmem& sm, int i, int n, int tid, bool act,
    const float4* st, const float4* ct, float4 tv4, float* __restrict__ out) {
    if (!act) return;
    const uint32_t* rows = reinterpret_cast<const uint32_t*>(
        s_buf + (size_t)(i & 1) * (ROWS * TT));
    float off = sm.off[i], tr = sm.tr[i];
    float4 acc;
    acc.x = fmaf(tr, tv4.x, off);
    acc.y = fmaf(tr, tv4.y, off);
    acc.z = fmaf(tr, tv4.z, off);
    acc.w = fmaf(tr, tv4.w, off);
#pragma unroll
    for (int c = 0; c < NCC; c++) {
        float u = sm.UV[i][c], v = sm.UV[i][5 + c];
        acc.x = fmaf(u, st[c].x, fmaf(v, ct[c].x, acc.x));
        acc.y = fmaf(u, st[c].y, fmaf(v, ct[c].y, acc.y));
        acc.z = fmaf(u, st[c].z, fmaf(v, ct[c].z, acc.z));
        acc.w = fmaf(u, st[c].w, fmaf(v, ct[c].w, acc.w));
    }
#pragma unroll
    for (int j = 0; j < ROWS; j++) {
        uint2 raw = *reinterpret_cast<const uint2*>(rows + j * 200 + 2 * tid);
        float w = sm.W[i][j];
        acc.x = fmaf(w, bf_lo(raw.x), acc.x);
        acc.y = fmaf(w, bf_hi(raw.x), acc.y);
        acc.z = fmaf(w, bf_lo(raw.y), acc.z);
        acc.w = fmaf(w, bf_hi(raw.y), acc.w);
    }
    reinterpret_cast<float4*>(out + (size_t)n * TT)[tid] = acc;
}

// ---------------- k_main_g4: gather4 path (4 TMA requests per stage) --------
__global__ void __launch_bounds__(128, 8)
k_main_g4(const __grid_constant__ CUtensorMap tmap,
          const int* __restrict__ idx,
          const float* __restrict__ coff,
          const float* __restrict__ ltr,
          const float* __restrict__ tv,
          float* __restrict__ out) {
    __shared__ MainSmem sm;
    int tid = threadIdx.x;
    int n0 = blockIdx.x * GG;
    bool act = (tid < T4);
    float4 st[NCC], ct[NCC], tv4;
    main_prologue(sm, idx, coff, ltr, tv, n0, tid, st, ct, tv4, act);
    __syncthreads();

    uint32_t full0 = smem_u32(&sm.full[0]);
    uint32_t bufb  = smem_u32(s_buf);

    auto issue = [&](int s) {
        uint32_t dst = bufb + (uint32_t)(s & 1) * STAGEBYTES;
        uint32_t mb  = full0 + (uint32_t)(s & 1) * 8;
        mbar_expect_tx(mb, STAGEBYTES);
        const int* r = sm.idxs[s];
#pragma unroll
        for (int q = 0; q < 4; q++) {
            g4(dst + (uint32_t)q * (4 * ROWBYTES), &tmap,
               r[4 * q], r[4 * q + 1], r[4 * q + 2], r[4 * q + 3], mb);
        }
    };

    if (tid == 0) issue(0);
    for (int i = 0; i < GG; i++) {
        if (tid == 0 && i + 1 < GG) issue(i + 1);
        mbar_wait(full0 + (uint32_t)(i & 1) * 8, (uint32_t)((i >> 1) & 1));
        stage_compute(sm, i, n0 + i, tid, act, st, ct, tv4, out);
        __syncthreads();
    }
}

// ---------------- k_main_fb: proven R7 bulk-copy fallback -------------------
__global__ void __launch_bounds__(128, 8)
k_main_fb(const int* __restrict__ idx,
          const float* __restrict__ coff,
          const float* __restrict__ ltr,
          const float* __restrict__ tv,
          float* __restrict__ out) {
    __shared__ MainSmem sm;
    int tid = threadIdx.x;
    int n0 = blockIdx.x * GG;
    bool act = (tid < T4);
    float4 st[NCC], ct[NCC], tv4;
    main_prologue(sm, idx, coff, ltr, tv, n0, tid, st, ct, tv4, act);
    __syncthreads();

    uint32_t full0 = smem_u32(&sm.full[0]);
    uint32_t bufb  = smem_u32(s_buf);

    auto issue = [&](int s) {
        uint32_t dst = bufb + (uint32_t)(s & 1) * STAGEBYTES;
        uint32_t mb  = full0 + (uint32_t)(s & 1) * 8;
        mbar_expect_tx(mb, STAGEBYTES);
#pragma unroll
        for (int k = 0; k < ROWS; k++) {
            bulk_g2s(dst + (uint32_t)k * ROWBYTES,
                     g_emd + (size_t)sm.idxs[s][k] * TT, ROWBYTES, mb);
        }
    };

    if (tid == 0) issue(0);
    for (int i = 0; i < GG; i++) {
        if (tid == 0 && i + 1 < GG) issue(i + 1);
        mbar_wait(full0 + (uint32_t)(i & 1) * 8, (uint32_t)((i >> 1) & 1));
        stage_compute(sm, i, n0 + i, tid, act, st, ct, tv4, out);
        __syncthreads();
    }
}

// ---------------- launch ----------------
typedef CUresult (*EncodeFn)(CUtensorMap*, CUtensorMapDataType, cuuint32_t,
                             void*, const cuuint64_t*, const cuuint64_t*,
                             const cuuint32_t*, const cuuint32_t*,
                             CUtensorMapInterleave, CUtensorMapSwizzle,
                             CUtensorMapL2promotion, CUtensorMapFloatOOBfill);

extern "C" void kernel_launch(void* const* d_in, const int* in_sizes, int n_in,
                              void* d_out, int out_size) {
    const float* tv   = (const float*)d_in[0];
    const float* coff = (const float*)d_in[1];
    const float* ltr  = (const float*)d_in[2];
    const float* emd  = (const float*)d_in[3];
    const int*   idx  = (const int*)  d_in[4];
    const float* nw   = (const float*)d_in[5];
    const float* lwv  = (const float*)d_in[6];
    const float* amp  = (const float*)d_in[7];
    const float* ph   = (const float*)d_in[8];
    const float* per  = (const float*)d_in[9];
    const float* esw  = (const float*)d_in[10];
    const float* lsw  = (const float*)d_in[11];
    float* out = (float*)d_out;

    k_pre<<<NB_PRE, 256>>>(emd, nw, lwv, esw, lsw, amp, ph, idx, tv, per);

    // Build gather4 tensormap: view g_emd as u32 tensor [NN rows x 200 cols]
    bool g4ok = false;
    CUtensorMap tmap;
    {
        void* fn = nullptr;
        cudaDriverEntryPointQueryResult qres;
        if (cudaGetDriverEntryPoint("cuTensorMapEncodeTiled", &fn,
                                    cudaEnableDefault, &qres) == cudaSuccess &&
            fn != nullptr) {
            void* gaddr = nullptr;
            if (cudaGetSymbolAddress(&gaddr, g_emd) == cudaSuccess) {
                cuuint64_t dims[2]    = {200, NN};
                cuuint64_t strides[1] = {ROWBYTES};   // 800 B between rows
                cuuint32_t box[2]     = {200, 1};
                cuuint32_t estr[2]    = {1, 1};
                CUresult r = ((EncodeFn)fn)(
                    &tmap, CU_TENSOR_MAP_DATA_TYPE_UINT32, 2, gaddr,
                    dims, strides, box, estr,
                    CU_TENSOR_MAP_INTERLEAVE_NONE, CU_TENSOR_MAP_SWIZZLE_NONE,
                    CU_TENSOR_MAP_L2_PROMOTION_L2_128B,
                    CU_TENSOR_MAP_FLOAT_OOB_FILL_NONE);
                g4ok = (r == CUDA_SUCCESS);
            }
        }
    }

    cudaFuncSetAttribute(k_main_g4, cudaFuncAttributeMaxDynamicSharedMemorySize,
                         2 * STAGEBYTES);
    cudaFuncSetAttribute(k_main_fb, cudaFuncAttributeMaxDynamicSharedMemorySize,
                         2 * STAGEBYTES);
    if (g4ok) {
        k_main_g4<<<NN / GG, 128, 2 * STAGEBYTES>>>(tmap, idx, coff, ltr, tv, out);
    } else {
        k_main_fb<<<NN / GG, 128, 2 * STAGEBYTES>>>(idx, coff, ltr, tv, out);
    }
}